// round 1
// baseline (speedup 1.0000x reference)
#include <cuda_runtime.h>
#include <cuda_bf16.h>
#include <math.h>

// Problem shapes (fixed by the dataset)
#define BATCH 4
#define SEQ   2048
#define HID   1024   // H
#define DIM   1024   // D
#define SCALE 0.03125f  // 1/sqrt(1024)

// Scratch (device globals; allocation in kernel_launch is forbidden)
__device__ float g_Q[(long)BATCH * SEQ * DIM];
__device__ float g_K[(long)BATCH * SEQ * DIM];
__device__ float g_V[(long)BATCH * SEQ * DIM];
__device__ float g_P[(long)BATCH * SEQ * SEQ];

// ---------------------------------------------------------------------------
// Tiled SGEMM: C = alpha * A @ B(^T)
//   A: [M, K] row-major (lda = K typically)
//   B: NN: [K, N] row-major; NT: [N, K] row-major (dot over contiguous K)
//   BM=BN=128, BK=8, 256 threads, 8x8 per-thread micro-tile.
//   CAUSAL_SKIP: skip blocks entirely above the diagonal (scores GEMM)
//   KBOUND:      k loop bounded by m0+BM (PV GEMM; P is zero beyond row idx)
// ---------------------------------------------------------------------------
template <bool TRANSB, bool CAUSAL_SKIP, bool KBOUND>
__global__ __launch_bounds__(256, 2)
void gemm128(const float* __restrict__ A, const float* __restrict__ B,
             float* __restrict__ C, int K, int lda, int ldb, int ldc,
             long sA, long sB, long sC, float alpha)
{
    constexpr int BM = 128, BN = 128, BK = 8;
    const int m0 = blockIdx.y * BM;
    const int n0 = blockIdx.x * BN;
    if (CAUSAL_SKIP && n0 > m0 + BM - 1) return;

    const int z = blockIdx.z;
    A += z * sA; B += z * sB; C += z * sC;

    __shared__ float As[BK][BM];
    __shared__ float Bs[BK][BN];

    const int tid  = threadIdx.x;
    const int tx   = tid & 15;   // 0..15  -> n micro
    const int ty   = tid >> 4;   // 0..15  -> m micro
    const int aRow = tid >> 1;         // 0..127
    const int aCol = (tid & 1) << 2;   // 0 or 4
    const int bRow = tid >> 5;         // 0..7   (NN)
    const int bCol = (tid & 31) << 2;  // 0..124 (NN)

    float acc[8][8];
    #pragma unroll
    for (int i = 0; i < 8; ++i)
        #pragma unroll
        for (int j = 0; j < 8; ++j) acc[i][j] = 0.f;

    int kEnd = K;
    if (KBOUND) kEnd = min(K, m0 + BM);

    for (int kt = 0; kt < kEnd; kt += BK) {
        // Load A tile (BM x BK), store transposed As[k][m]
        float4 av = *(const float4*)(A + (long)(m0 + aRow) * lda + kt + aCol);
        As[aCol + 0][aRow] = av.x;
        As[aCol + 1][aRow] = av.y;
        As[aCol + 2][aRow] = av.z;
        As[aCol + 3][aRow] = av.w;

        if (TRANSB) {
            // B is [N, K] row-major: tile (BN x BK), store Bs[k][n]
            float4 bv = *(const float4*)(B + (long)(n0 + aRow) * ldb + kt + aCol);
            Bs[aCol + 0][aRow] = bv.x;
            Bs[aCol + 1][aRow] = bv.y;
            Bs[aCol + 2][aRow] = bv.z;
            Bs[aCol + 3][aRow] = bv.w;
        } else {
            // B is [K, N] row-major: tile (BK x BN)
            float4 bv = *(const float4*)(B + (long)(kt + bRow) * ldb + n0 + bCol);
            *(float4*)&Bs[bRow][bCol] = bv;
        }
        __syncthreads();

        #pragma unroll
        for (int k = 0; k < BK; ++k) {
            float4 a0 = *(const float4*)&As[k][ty * 8];
            float4 a1 = *(const float4*)&As[k][ty * 8 + 4];
            float4 b0 = *(const float4*)&Bs[k][tx * 8];
            float4 b1 = *(const float4*)&Bs[k][tx * 8 + 4];
            float aF[8] = {a0.x, a0.y, a0.z, a0.w, a1.x, a1.y, a1.z, a1.w};
            float bF[8] = {b0.x, b0.y, b0.z, b0.w, b1.x, b1.y, b1.z, b1.w};
            #pragma unroll
            for (int i = 0; i < 8; ++i)
                #pragma unroll
                for (int j = 0; j < 8; ++j)
                    acc[i][j] += aF[i] * bF[j];
        }
        __syncthreads();
    }

    // Epilogue: float4 stores
    #pragma unroll
    for (int i = 0; i < 8; ++i) {
        float* crow = C + (long)(m0 + ty * 8 + i) * ldc + n0 + tx * 8;
        float4 v0 = make_float4(alpha * acc[i][0], alpha * acc[i][1],
                                alpha * acc[i][2], alpha * acc[i][3]);
        float4 v1 = make_float4(alpha * acc[i][4], alpha * acc[i][5],
                                alpha * acc[i][6], alpha * acc[i][7]);
        *(float4*)(crow)     = v0;
        *(float4*)(crow + 4) = v1;
    }
}

// ---------------------------------------------------------------------------
// Causal softmax over one row of the scores buffer.
// Row i: softmax over [0, i], zeros over (i, S) so PV can be a dense GEMM.
// ---------------------------------------------------------------------------
__global__ __launch_bounds__(256)
void softmax_causal(float* __restrict__ P)
{
    const int S = SEQ;
    const int i = blockIdx.x;
    const int b = blockIdx.y;
    float* row = P + ((long)b * S + (long)i) * S;

    __shared__ float buf[SEQ];
    __shared__ float red[256];
    const int tid = threadIdx.x;
    const int L = i + 1;

    float m = -3.0e38f;
    for (int j = tid; j < L; j += 256) {
        float v = row[j];
        buf[j] = v;
        m = fmaxf(m, v);
    }
    red[tid] = m;
    __syncthreads();
    #pragma unroll
    for (int s = 128; s > 0; s >>= 1) {
        if (tid < s) red[tid] = fmaxf(red[tid], red[tid + s]);
        __syncthreads();
    }
    m = red[0];
    __syncthreads();

    float sum = 0.f;
    for (int j = tid; j < L; j += 256) {
        float e = expf(buf[j] - m);
        buf[j] = e;
        sum += e;
    }
    red[tid] = sum;
    __syncthreads();
    #pragma unroll
    for (int s = 128; s > 0; s >>= 1) {
        if (tid < s) red[tid] += red[tid + s];
        __syncthreads();
    }
    const float inv = 1.0f / red[0];

    for (int j = tid; j < S; j += 256)
        row[j] = (j < L) ? buf[j] * inv : 0.f;
}

extern "C" void kernel_launch(void* const* d_in, const int* in_sizes, int n_in,
                              void* d_out, int out_size)
{
    (void)in_sizes; (void)n_in; (void)out_size;
    const float* X  = (const float*)d_in[0];
    const float* Wq = (const float*)d_in[1];
    const float* Wk = (const float*)d_in[2];
    const float* Wv = (const float*)d_in[3];
    float* out = (float*)d_out;

    void *qp, *kp, *vp, *pp;
    cudaGetSymbolAddress(&qp, g_Q);
    cudaGetSymbolAddress(&kp, g_K);
    cudaGetSymbolAddress(&vp, g_V);
    cudaGetSymbolAddress(&pp, g_P);
    float* Q = (float*)qp;
    float* Kt = (float*)kp;
    float* V = (float*)vp;
    float* P = (float*)pp;

    const long perQ = (long)SEQ * DIM;   // per-batch Q/K/V/out stride
    const long perP = (long)SEQ * SEQ;   // per-batch scores stride

    // 1) QKV projections: [B*S, H] @ [H, D]  (M=8192, N=1024, K=1024)
    {
        dim3 grid(DIM / 128, (BATCH * SEQ) / 128, 1);
        gemm128<false, false, false><<<grid, 256>>>(
            X, Wq, Q, HID, HID, DIM, DIM, 0, 0, 0, 1.0f);
        gemm128<false, false, false><<<grid, 256>>>(
            X, Wk, Kt, HID, HID, DIM, DIM, 0, 0, 0, 1.0f);
        gemm128<false, false, false><<<grid, 256>>>(
            X, Wv, V, HID, HID, DIM, DIM, 0, 0, 0, 1.0f);
    }

    // 2) scores = (Q @ K^T) * (1/sqrt(D)), lower-triangular blocks only
    {
        dim3 grid(SEQ / 128, SEQ / 128, BATCH);
        gemm128<true, true, false><<<grid, 256>>>(
            Q, Kt, P, DIM, DIM, DIM, SEQ, perQ, perQ, perP, SCALE);
    }

    // 3) causal softmax per row; zeros above the diagonal
    {
        dim3 grid(SEQ, BATCH);
        softmax_causal<<<grid, 256>>>(P);
    }

    // 4) out = P @ V, K bounded per M-tile by causality
    {
        dim3 grid(DIM / 128, SEQ / 128, BATCH);
        gemm128<false, false, true><<<grid, 256>>>(
            P, V, out, SEQ, SEQ, DIM, DIM, perP, perQ, perQ, 1.0f);
    }
}

// round 3
// speedup vs baseline: 2.0027x; 2.0027x over previous
#include <cuda_runtime.h>
#include <cuda_bf16.h>
#include <cstdint>
#include <math.h>

// Problem shapes (fixed by the dataset)
#define BATCH 4
#define SEQ   2048
#define HID   1024
#define DIM   1024
#define SCALE 0.03125f   // 1/sqrt(1024)

// Scratch (device globals; runtime allocation is forbidden)
__device__ float g_Q[(long)BATCH * SEQ * DIM];
__device__ float g_K[(long)BATCH * SEQ * DIM];
__device__ float g_V[(long)BATCH * SEQ * DIM];
__device__ float g_P[(long)BATCH * SEQ * SEQ];

// ---------------------------------------------------------------------------
// Warp MMA helpers (baseline PTX — works on plain sm_103 target)
// ---------------------------------------------------------------------------
__device__ __forceinline__ uint32_t smem_u32(const void* p) {
    uint32_t a;
    asm("{ .reg .u64 t; cvta.to.shared.u64 t, %1; cvt.u32.u64 %0, t; }"
        : "=r"(a) : "l"(p));
    return a;
}

__device__ __forceinline__ void ldsm_x4(uint32_t* r, uint32_t addr) {
    asm volatile("ldmatrix.sync.aligned.m8n8.x4.shared.b16 {%0,%1,%2,%3}, [%4];"
                 : "=r"(r[0]), "=r"(r[1]), "=r"(r[2]), "=r"(r[3]) : "r"(addr));
}
__device__ __forceinline__ void ldsm_x4_t(uint32_t* r, uint32_t addr) {
    asm volatile("ldmatrix.sync.aligned.m8n8.x4.trans.shared.b16 {%0,%1,%2,%3}, [%4];"
                 : "=r"(r[0]), "=r"(r[1]), "=r"(r[2]), "=r"(r[3]) : "r"(addr));
}

// D(f32) += A(bf16) * B(bf16); m16n8k16, A row-major, B col-major fragments
__device__ __forceinline__ void mma_bf16(float* c, const uint32_t* a,
                                         const uint32_t* b) {
    asm volatile(
        "mma.sync.aligned.m16n8k16.row.col.f32.bf16.bf16.f32 "
        "{%0,%1,%2,%3}, {%4,%5,%6,%7}, {%8,%9}, {%0,%1,%2,%3};"
        : "+f"(c[0]), "+f"(c[1]), "+f"(c[2]), "+f"(c[3])
        : "r"(a[0]), "r"(a[1]), "r"(a[2]), "r"(a[3]), "r"(b[0]), "r"(b[1]));
}

// Split fp32x4 -> hi/lo bf16x4, stored as two 8-byte writes each
__device__ __forceinline__ void split_store(__nv_bfloat16* hiP, __nv_bfloat16* loP,
                                            float4 v) {
    __nv_bfloat16 hx = __float2bfloat16(v.x);
    __nv_bfloat16 hy = __float2bfloat16(v.y);
    __nv_bfloat16 hz = __float2bfloat16(v.z);
    __nv_bfloat16 hw = __float2bfloat16(v.w);
    __nv_bfloat162 h0 = __halves2bfloat162(hx, hy);
    __nv_bfloat162 h1 = __halves2bfloat162(hz, hw);
    __nv_bfloat162 l0 = __halves2bfloat162(
        __float2bfloat16(v.x - __bfloat162float(hx)),
        __float2bfloat16(v.y - __bfloat162float(hy)));
    __nv_bfloat162 l1 = __halves2bfloat162(
        __float2bfloat16(v.z - __bfloat162float(hz)),
        __float2bfloat16(v.w - __bfloat162float(hw)));
    uint2 hu, lu;
    hu.x = reinterpret_cast<uint32_t&>(h0);
    hu.y = reinterpret_cast<uint32_t&>(h1);
    lu.x = reinterpret_cast<uint32_t&>(l0);
    lu.y = reinterpret_cast<uint32_t&>(l1);
    *reinterpret_cast<uint2*>(hiP) = hu;
    *reinterpret_cast<uint2*>(loP) = lu;
}

// ---------------------------------------------------------------------------
// HMMA GEMM: C = alpha * A @ op(B)
//   A: [M,K] row-major. TRANSB: B is [N,K] row-major (NT); else [K,N] (NN).
//   BM=BN=128, BK=32. 256 threads, 8 warps (4m x 2n), warp tile 32x64.
//   3-term Markidis bf16 split (AhiBhi + AhiBlo + AloBhi) for fp32 accuracy.
// ---------------------------------------------------------------------------
#define ASTR 40    // bf16 row stride of A / B(NT) tiles: 80B -> ldmatrix conflict-free
#define BSTR 136   // bf16 row stride of B(NN) [k][n] tile: 272B -> conflict-free

template <bool TRANSB, bool CAUSAL_SKIP, bool KBOUND>
__global__ __launch_bounds__(256)
void gemm_mma(const float* __restrict__ A, const float* __restrict__ B,
              float* __restrict__ C, int K, int lda, int ldb, int ldc,
              long sA, long sB, long sC, float alpha)
{
    const int m0 = blockIdx.y * 128;
    const int n0 = blockIdx.x * 128;
    if (CAUSAL_SKIP && n0 > m0 + 127) return;

    A += blockIdx.z * sA; B += blockIdx.z * sB; C += blockIdx.z * sC;

    constexpr int BELEMS = TRANSB ? 128 * ASTR : 32 * BSTR;
    __shared__ __align__(16) __nv_bfloat16 sAhi[128 * ASTR];
    __shared__ __align__(16) __nv_bfloat16 sAlo[128 * ASTR];
    __shared__ __align__(16) __nv_bfloat16 sBhi[BELEMS];
    __shared__ __align__(16) __nv_bfloat16 sBlo[BELEMS];

    const int tid  = threadIdx.x;
    const int lane = tid & 31;
    const int wm   = ((tid >> 5) & 3) * 32;   // warp m-offset in tile
    const int wn   = (tid >> 7) * 64;         // warp n-offset in tile

    const uint32_t aHiB = smem_u32(sAhi);
    const uint32_t aLoB = smem_u32(sAlo);
    const uint32_t bHiB = smem_u32(sBhi);
    const uint32_t bLoB = smem_u32(sBlo);

    float acc[2][8][4];
    #pragma unroll
    for (int i = 0; i < 2; ++i)
        #pragma unroll
        for (int j = 0; j < 8; ++j)
            #pragma unroll
            for (int t = 0; t < 4; ++t) acc[i][j][t] = 0.f;

    int kEnd = K;
    if (KBOUND) kEnd = min(K, m0 + 128);

    for (int kt = 0; kt < kEnd; kt += 32) {
        // ---- stage A tile [128 x 32] fp32 -> hi/lo bf16 ----
        #pragma unroll
        for (int i = 0; i < 4; ++i) {
            int vid = tid + i * 256;
            int r = vid >> 3;
            int c = (vid & 7) * 4;
            float4 v = *(const float4*)(A + (long)(m0 + r) * lda + kt + c);
            split_store(&sAhi[r * ASTR + c], &sAlo[r * ASTR + c], v);
        }
        // ---- stage B tile ----
        if (TRANSB) {
            // B is [N,K] row-major -> tile [n][k], stride ASTR
            #pragma unroll
            for (int i = 0; i < 4; ++i) {
                int vid = tid + i * 256;
                int r = vid >> 3;
                int c = (vid & 7) * 4;
                float4 v = *(const float4*)(B + (long)(n0 + r) * ldb + kt + c);
                split_store(&sBhi[r * ASTR + c], &sBlo[r * ASTR + c], v);
            }
        } else {
            // B is [K,N] row-major -> tile [k][n] (natural), stride BSTR
            #pragma unroll
            for (int i = 0; i < 4; ++i) {
                int vid = tid + i * 256;
                int kk = vid >> 5;
                int n4 = (vid & 31) * 4;
                float4 v = *(const float4*)(B + (long)(kt + kk) * ldb + n0 + n4);
                split_store(&sBhi[kk * BSTR + n4], &sBlo[kk * BSTR + n4], v);
            }
        }
        __syncthreads();

        #pragma unroll
        for (int ks = 0; ks < 2; ++ks) {
            // A fragments: 2 m-tiles, hi and lo
            uint32_t aH[2][4], aL[2][4];
            #pragma unroll
            for (int mt = 0; mt < 2; ++mt) {
                uint32_t off =
                    ((uint32_t)(wm + mt * 16 + (lane & 15)) * ASTR +
                     ks * 16 + (lane >> 4) * 8) * 2;
                ldsm_x4(aH[mt], aHiB + off);
                ldsm_x4(aL[mt], aLoB + off);
            }
            // B fragments: 4 pairs of n-tiles
            #pragma unroll
            for (int np = 0; np < 4; ++np) {
                uint32_t bH[4], bL[4];
                if (TRANSB) {
                    uint32_t nrow = wn + np * 16 + (lane & 7) + (lane >> 4) * 8;
                    uint32_t off = (nrow * ASTR + ks * 16 + ((lane >> 3) & 1) * 8) * 2;
                    ldsm_x4(bH, bHiB + off);
                    ldsm_x4(bL, bLoB + off);
                } else {
                    uint32_t krow = ks * 16 + (lane & 15);
                    uint32_t ncol = wn + np * 16 + (lane >> 4) * 8;
                    uint32_t off = (krow * BSTR + ncol) * 2;
                    ldsm_x4_t(bH, bHiB + off);
                    ldsm_x4_t(bL, bLoB + off);
                }
                #pragma unroll
                for (int h = 0; h < 2; ++h) {
                    #pragma unroll
                    for (int mt = 0; mt < 2; ++mt) {
                        float* c = acc[mt][np * 2 + h];
                        mma_bf16(c, aH[mt], bH + h * 2);
                        mma_bf16(c, aH[mt], bL + h * 2);
                        mma_bf16(c, aL[mt], bH + h * 2);
                    }
                }
            }
        }
        __syncthreads();
    }

    // ---- epilogue: registers -> global (float2 stores) ----
    #pragma unroll
    for (int mt = 0; mt < 2; ++mt) {
        #pragma unroll
        for (int nt = 0; nt < 8; ++nt) {
            int row = m0 + wm + mt * 16 + (lane >> 2);
            int col = n0 + wn + nt * 8 + (lane & 3) * 2;
            float2 v0 = make_float2(alpha * acc[mt][nt][0], alpha * acc[mt][nt][1]);
            float2 v1 = make_float2(alpha * acc[mt][nt][2], alpha * acc[mt][nt][3]);
            *(float2*)(C + (long)row * ldc + col) = v0;
            *(float2*)(C + (long)(row + 8) * ldc + col) = v1;
        }
    }
}

// ---------------------------------------------------------------------------
// Causal softmax over one row: softmax over [0,i], zeros over (i,S).
// ---------------------------------------------------------------------------
__global__ __launch_bounds__(256)
void softmax_causal(float* __restrict__ P)
{
    const int S = SEQ;
    const int i = blockIdx.x;
    const int b = blockIdx.y;
    float* row = P + ((long)b * S + (long)i) * S;

    __shared__ float buf[SEQ];
    __shared__ float red[256];
    const int tid = threadIdx.x;
    const int L = i + 1;

    float m = -3.0e38f;
    for (int j = tid; j < L; j += 256) {
        float v = row[j];
        buf[j] = v;
        m = fmaxf(m, v);
    }
    red[tid] = m;
    __syncthreads();
    #pragma unroll
    for (int s = 128; s > 0; s >>= 1) {
        if (tid < s) red[tid] = fmaxf(red[tid], red[tid + s]);
        __syncthreads();
    }
    m = red[0];
    __syncthreads();

    float sum = 0.f;
    for (int j = tid; j < L; j += 256) {
        float e = expf(buf[j] - m);
        buf[j] = e;
        sum += e;
    }
    red[tid] = sum;
    __syncthreads();
    #pragma unroll
    for (int s = 128; s > 0; s >>= 1) {
        if (tid < s) red[tid] += red[tid + s];
        __syncthreads();
    }
    const float inv = 1.0f / red[0];

    for (int j = tid; j < S; j += 256)
        row[j] = (j < L) ? buf[j] * inv : 0.f;
}

// ---------------------------------------------------------------------------
extern "C" void kernel_launch(void* const* d_in, const int* in_sizes, int n_in,
                              void* d_out, int out_size)
{
    (void)in_sizes; (void)n_in; (void)out_size;
    const float* X  = (const float*)d_in[0];
    const float* Wq = (const float*)d_in[1];
    const float* Wk = (const float*)d_in[2];
    const float* Wv = (const float*)d_in[3];
    float* out = (float*)d_out;

    void *qp, *kp, *vp, *pp;
    cudaGetSymbolAddress(&qp, g_Q);
    cudaGetSymbolAddress(&kp, g_K);
    cudaGetSymbolAddress(&vp, g_V);
    cudaGetSymbolAddress(&pp, g_P);
    float* Q  = (float*)qp;
    float* Kt = (float*)kp;
    float* V  = (float*)vp;
    float* P  = (float*)pp;

    const long perQ = (long)SEQ * DIM;
    const long perP = (long)SEQ * SEQ;

    // 1) QKV projections: [B*S, H] @ [H, D]
    {
        dim3 grid(DIM / 128, (BATCH * SEQ) / 128, 1);
        gemm_mma<false, false, false><<<grid, 256>>>(
            X, Wq, Q, HID, HID, DIM, DIM, 0, 0, 0, 1.0f);
        gemm_mma<false, false, false><<<grid, 256>>>(
            X, Wk, Kt, HID, HID, DIM, DIM, 0, 0, 0, 1.0f);
        gemm_mma<false, false, false><<<grid, 256>>>(
            X, Wv, V, HID, HID, DIM, DIM, 0, 0, 0, 1.0f);
    }

    // 2) scores = (Q @ K^T) * (1/sqrt(D)), lower-triangular blocks only
    {
        dim3 grid(SEQ / 128, SEQ / 128, BATCH);
        gemm_mma<true, true, false><<<grid, 256>>>(
            Q, Kt, P, DIM, DIM, DIM, SEQ, perQ, perQ, perP, SCALE);
    }

    // 3) causal softmax; zeros above the diagonal
    {
        dim3 grid(SEQ, BATCH);
        softmax_causal<<<grid, 256>>>(P);
    }

    // 4) out = P @ V, K bounded per M-tile by causality
    {
        dim3 grid(DIM / 128, SEQ / 128, BATCH);
        gemm_mma<false, false, true><<<grid, 256>>>(
            P, V, out, SEQ, SEQ, DIM, DIM, perP, perQ, perQ, 1.0f);
    }
}

// round 4
// speedup vs baseline: 2.4957x; 1.2461x over previous
#include <cuda_runtime.h>
#include <cuda_bf16.h>
#include <cstdint>
#include <math.h>

// Problem shapes (fixed by the dataset)
#define BATCH 4
#define SEQ   2048
#define HID   1024
#define DIM   1024
#define SCALE 0.03125f   // 1/sqrt(1024)

// Scratch (device globals; runtime allocation is forbidden)
__device__ float g_Q[(long)BATCH * SEQ * DIM];
__device__ float g_K[(long)BATCH * SEQ * DIM];
__device__ float g_V[(long)BATCH * SEQ * DIM];
__device__ float g_P[(long)BATCH * SEQ * SEQ];

// ---------------------------------------------------------------------------
// Warp MMA helpers (baseline PTX — works on plain sm_103 target)
// ---------------------------------------------------------------------------
__device__ __forceinline__ uint32_t smem_u32(const void* p) {
    uint32_t a;
    asm("{ .reg .u64 t; cvta.to.shared.u64 t, %1; cvt.u32.u64 %0, t; }"
        : "=r"(a) : "l"(p));
    return a;
}

__device__ __forceinline__ void ldsm_x4(uint32_t* r, uint32_t addr) {
    asm volatile("ldmatrix.sync.aligned.m8n8.x4.shared.b16 {%0,%1,%2,%3}, [%4];"
                 : "=r"(r[0]), "=r"(r[1]), "=r"(r[2]), "=r"(r[3]) : "r"(addr));
}
__device__ __forceinline__ void ldsm_x4_t(uint32_t* r, uint32_t addr) {
    asm volatile("ldmatrix.sync.aligned.m8n8.x4.trans.shared.b16 {%0,%1,%2,%3}, [%4];"
                 : "=r"(r[0]), "=r"(r[1]), "=r"(r[2]), "=r"(r[3]) : "r"(addr));
}

// D(f32) += A(bf16) * B(bf16); m16n8k16, A row-major, B col-major fragments
__device__ __forceinline__ void mma_bf16(float* c, const uint32_t* a,
                                         const uint32_t* b) {
    asm volatile(
        "mma.sync.aligned.m16n8k16.row.col.f32.bf16.bf16.f32 "
        "{%0,%1,%2,%3}, {%4,%5,%6,%7}, {%8,%9}, {%0,%1,%2,%3};"
        : "+f"(c[0]), "+f"(c[1]), "+f"(c[2]), "+f"(c[3])
        : "r"(a[0]), "r"(a[1]), "r"(a[2]), "r"(a[3]), "r"(b[0]), "r"(b[1]));
}

// Split fp32x4 -> hi/lo bf16x4, stored as two 8-byte writes each
__device__ __forceinline__ void split_store(__nv_bfloat16* hiP, __nv_bfloat16* loP,
                                            float4 v) {
    __nv_bfloat16 hx = __float2bfloat16(v.x);
    __nv_bfloat16 hy = __float2bfloat16(v.y);
    __nv_bfloat16 hz = __float2bfloat16(v.z);
    __nv_bfloat16 hw = __float2bfloat16(v.w);
    __nv_bfloat162 h0 = __halves2bfloat162(hx, hy);
    __nv_bfloat162 h1 = __halves2bfloat162(hz, hw);
    __nv_bfloat162 l0 = __halves2bfloat162(
        __float2bfloat16(v.x - __bfloat162float(hx)),
        __float2bfloat16(v.y - __bfloat162float(hy)));
    __nv_bfloat162 l1 = __halves2bfloat162(
        __float2bfloat16(v.z - __bfloat162float(hz)),
        __float2bfloat16(v.w - __bfloat162float(hw)));
    uint2 hu, lu;
    hu.x = reinterpret_cast<uint32_t&>(h0);
    hu.y = reinterpret_cast<uint32_t&>(h1);
    lu.x = reinterpret_cast<uint32_t&>(l0);
    lu.y = reinterpret_cast<uint32_t&>(l1);
    *reinterpret_cast<uint2*>(hiP) = hu;
    *reinterpret_cast<uint2*>(loP) = lu;
}

// ---------------------------------------------------------------------------
// HMMA GEMM with register-prefetch software pipeline:
//   C = alpha * A @ op(B)
//   A: [M,K] row-major. TRANSB: B is [N,K] row-major (NT); else [K,N] (NN).
//   BM=BN=128, BK=32. 256 threads, 8 warps (4m x 2n), warp tile 32x64.
//   Loop: STS(cur regs) -> sync -> LDG(next->regs) -> MMA(smem) -> sync.
//   Global-load latency is hidden behind the MMA phase.
// ---------------------------------------------------------------------------
#define ASTR 40    // bf16 row stride of A / B(NT) tiles: 80B -> ldmatrix conflict-free
#define BSTR 136   // bf16 row stride of B(NN) [k][n] tile: 272B -> conflict-free

template <bool TRANSB, bool CAUSAL_SKIP, bool KBOUND>
__global__ __launch_bounds__(256)
void gemm_mma(const float* __restrict__ A, const float* __restrict__ B,
              float* __restrict__ C, int K, int lda, int ldb, int ldc,
              long sA, long sB, long sC, float alpha)
{
    const int m0 = blockIdx.y * 128;
    const int n0 = blockIdx.x * 128;
    if (CAUSAL_SKIP && n0 > m0 + 127) return;

    A += blockIdx.z * sA; B += blockIdx.z * sB; C += blockIdx.z * sC;

    constexpr int BELEMS = TRANSB ? 128 * ASTR : 32 * BSTR;
    __shared__ __align__(16) __nv_bfloat16 sAhi[128 * ASTR];
    __shared__ __align__(16) __nv_bfloat16 sAlo[128 * ASTR];
    __shared__ __align__(16) __nv_bfloat16 sBhi[BELEMS];
    __shared__ __align__(16) __nv_bfloat16 sBlo[BELEMS];

    const int tid  = threadIdx.x;
    const int lane = tid & 31;
    const int wm   = ((tid >> 5) & 3) * 32;   // warp m-offset in tile
    const int wn   = (tid >> 7) * 64;         // warp n-offset in tile

    const uint32_t aHiB = smem_u32(sAhi);
    const uint32_t aLoB = smem_u32(sAlo);
    const uint32_t bHiB = smem_u32(sBhi);
    const uint32_t bLoB = smem_u32(sBlo);

    // Per-thread load coordinates (loop-invariant)
    const int ar = tid >> 3;             // A/B(NT) row 0..127 (vid base)
    const int ac = (tid & 7) * 4;        // A/B(NT) col base
    const int bk = tid >> 5;             // B(NN) k row base
    const int bn = (tid & 31) * 4;       // B(NN) n col base

    float acc[2][8][4];
    #pragma unroll
    for (int i = 0; i < 2; ++i)
        #pragma unroll
        for (int j = 0; j < 8; ++j)
            #pragma unroll
            for (int t = 0; t < 4; ++t) acc[i][j][t] = 0.f;

    int kEnd = K;
    if (KBOUND) kEnd = min(K, m0 + 128);

    float4 rA[4], rB[4];

    // ---- prologue: load first tile into registers ----
    #pragma unroll
    for (int i = 0; i < 4; ++i) {
        int r = ar + i * 32;
        rA[i] = *(const float4*)(A + (long)(m0 + r) * lda + ac);
        if (TRANSB) {
            rB[i] = *(const float4*)(B + (long)(n0 + r) * ldb + ac);
        } else {
            int kk = bk + i * 8;
            rB[i] = *(const float4*)(B + (long)kk * ldb + n0 + bn);
        }
    }

    for (int kt = 0; kt < kEnd; kt += 32) {
        // ---- store current tile (registers -> smem, with hi/lo split) ----
        #pragma unroll
        for (int i = 0; i < 4; ++i) {
            int r = ar + i * 32;
            split_store(&sAhi[r * ASTR + ac], &sAlo[r * ASTR + ac], rA[i]);
            if (TRANSB) {
                split_store(&sBhi[r * ASTR + ac], &sBlo[r * ASTR + ac], rB[i]);
            } else {
                int kk = bk + i * 8;
                split_store(&sBhi[kk * BSTR + bn], &sBlo[kk * BSTR + bn], rB[i]);
            }
        }
        __syncthreads();

        // ---- issue next tile's global loads (latency hidden by MMA) ----
        const int ktn = kt + 32;
        if (ktn < kEnd) {
            #pragma unroll
            for (int i = 0; i < 4; ++i) {
                int r = ar + i * 32;
                rA[i] = *(const float4*)(A + (long)(m0 + r) * lda + ktn + ac);
                if (TRANSB) {
                    rB[i] = *(const float4*)(B + (long)(n0 + r) * ldb + ktn + ac);
                } else {
                    int kk = ktn + bk + i * 8;
                    rB[i] = *(const float4*)(B + (long)kk * ldb + n0 + bn);
                }
            }
        }

        // ---- MMA over the staged tile ----
        #pragma unroll
        for (int ks = 0; ks < 2; ++ks) {
            uint32_t aH[2][4], aL[2][4];
            #pragma unroll
            for (int mt = 0; mt < 2; ++mt) {
                uint32_t off =
                    ((uint32_t)(wm + mt * 16 + (lane & 15)) * ASTR +
                     ks * 16 + (lane >> 4) * 8) * 2;
                ldsm_x4(aH[mt], aHiB + off);
                ldsm_x4(aL[mt], aLoB + off);
            }
            #pragma unroll
            for (int np = 0; np < 4; ++np) {
                uint32_t bH[4], bL[4];
                if (TRANSB) {
                    uint32_t nrow = wn + np * 16 + (lane & 7) + (lane >> 4) * 8;
                    uint32_t off = (nrow * ASTR + ks * 16 + ((lane >> 3) & 1) * 8) * 2;
                    ldsm_x4(bH, bHiB + off);
                    ldsm_x4(bL, bLoB + off);
                } else {
                    uint32_t krow = ks * 16 + (lane & 15);
                    uint32_t ncol = wn + np * 16 + (lane >> 4) * 8;
                    uint32_t off = (krow * BSTR + ncol) * 2;
                    ldsm_x4_t(bH, bHiB + off);
                    ldsm_x4_t(bL, bLoB + off);
                }
                #pragma unroll
                for (int h = 0; h < 2; ++h) {
                    #pragma unroll
                    for (int mt = 0; mt < 2; ++mt) {
                        float* c = acc[mt][np * 2 + h];
                        mma_bf16(c, aH[mt], bH + h * 2);
                        mma_bf16(c, aH[mt], bL + h * 2);
                        mma_bf16(c, aL[mt], bH + h * 2);
                    }
                }
            }
        }
        __syncthreads();
    }

    // ---- epilogue: registers -> global (float2 stores) ----
    #pragma unroll
    for (int mt = 0; mt < 2; ++mt) {
        #pragma unroll
        for (int nt = 0; nt < 8; ++nt) {
            int row = m0 + wm + mt * 16 + (lane >> 2);
            int col = n0 + wn + nt * 8 + (lane & 3) * 2;
            float2 v0 = make_float2(alpha * acc[mt][nt][0], alpha * acc[mt][nt][1]);
            float2 v1 = make_float2(alpha * acc[mt][nt][2], alpha * acc[mt][nt][3]);
            *(float2*)(C + (long)row * ldc + col) = v0;
            *(float2*)(C + (long)(row + 8) * ldc + col) = v1;
        }
    }
}

// ---------------------------------------------------------------------------
// Causal softmax over one row: softmax over [0,i], zeros over (i,S).
// ---------------------------------------------------------------------------
__global__ __launch_bounds__(256)
void softmax_causal(float* __restrict__ P)
{
    const int S = SEQ;
    const int i = blockIdx.x;
    const int b = blockIdx.y;
    float* row = P + ((long)b * S + (long)i) * S;

    __shared__ float buf[SEQ];
    __shared__ float red[256];
    const int tid = threadIdx.x;
    const int L = i + 1;

    float m = -3.0e38f;
    for (int j = tid; j < L; j += 256) {
        float v = row[j];
        buf[j] = v;
        m = fmaxf(m, v);
    }
    red[tid] = m;
    __syncthreads();
    #pragma unroll
    for (int s = 128; s > 0; s >>= 1) {
        if (tid < s) red[tid] = fmaxf(red[tid], red[tid + s]);
        __syncthreads();
    }
    m = red[0];
    __syncthreads();

    float sum = 0.f;
    for (int j = tid; j < L; j += 256) {
        float e = expf(buf[j] - m);
        buf[j] = e;
        sum += e;
    }
    red[tid] = sum;
    __syncthreads();
    #pragma unroll
    for (int s = 128; s > 0; s >>= 1) {
        if (tid < s) red[tid] += red[tid + s];
        __syncthreads();
    }
    const float inv = 1.0f / red[0];

    for (int j = tid; j < S; j += 256)
        row[j] = (j < L) ? buf[j] * inv : 0.f;
}

// ---------------------------------------------------------------------------
extern "C" void kernel_launch(void* const* d_in, const int* in_sizes, int n_in,
                              void* d_out, int out_size)
{
    (void)in_sizes; (void)n_in; (void)out_size;
    const float* X  = (const float*)d_in[0];
    const float* Wq = (const float*)d_in[1];
    const float* Wk = (const float*)d_in[2];
    const float* Wv = (const float*)d_in[3];
    float* out = (float*)d_out;

    void *qp, *kp, *vp, *pp;
    cudaGetSymbolAddress(&qp, g_Q);
    cudaGetSymbolAddress(&kp, g_K);
    cudaGetSymbolAddress(&vp, g_V);
    cudaGetSymbolAddress(&pp, g_P);
    float* Q  = (float*)qp;
    float* Kt = (float*)kp;
    float* V  = (float*)vp;
    float* P  = (float*)pp;

    const long perQ = (long)SEQ * DIM;
    const long perP = (long)SEQ * SEQ;

    // 1) QKV projections: [B*S, H] @ [H, D]
    {
        dim3 grid(DIM / 128, (BATCH * SEQ) / 128, 1);
        gemm_mma<false, false, false><<<grid, 256>>>(
            X, Wq, Q, HID, HID, DIM, DIM, 0, 0, 0, 1.0f);
        gemm_mma<false, false, false><<<grid, 256>>>(
            X, Wk, Kt, HID, HID, DIM, DIM, 0, 0, 0, 1.0f);
        gemm_mma<false, false, false><<<grid, 256>>>(
            X, Wv, V, HID, HID, DIM, DIM, 0, 0, 0, 1.0f);
    }

    // 2) scores = (Q @ K^T) * (1/sqrt(D)), lower-triangular blocks only
    {
        dim3 grid(SEQ / 128, SEQ / 128, BATCH);
        gemm_mma<true, true, false><<<grid, 256>>>(
            Q, Kt, P, DIM, DIM, DIM, SEQ, perQ, perQ, perP, SCALE);
    }

    // 3) causal softmax; zeros above the diagonal
    {
        dim3 grid(SEQ, BATCH);
        softmax_causal<<<grid, 256>>>(P);
    }

    // 4) out = P @ V, K bounded per M-tile by causality
    {
        dim3 grid(DIM / 128, SEQ / 128, BATCH);
        gemm_mma<false, false, true><<<grid, 256>>>(
            P, V, out, SEQ, SEQ, DIM, DIM, perP, perQ, perQ, 1.0f);
    }
}